// round 11
// baseline (speedup 1.0000x reference)
#include <cuda_runtime.h>
#include <cuda_bf16.h>
#include <cstdint>

// Problem: x [16, 256, 128, 128] f32.
//  1) weight[b,c] = mean over H,W
//  2) idx[b,:] = argsort(weight[b]) ascending, take first 16 (stable)
//  3) out[b,k,:,:] = x[b, idx[b,k], :, :]
//
// R11: persistent kernel, grid = 1184 (148 SMs x 8 blocks), dynamic work
// distribution via per-batch ticket pools:
//  - Phase A: pop mean-plane tickets (16 pools of 256). Perfect balance
//    removes the 3.46-wave quantization that cost the fixed-grid mean pass
//    ~3us (its 4th wave ran at 46% occupancy). Last finisher per batch does
//    the stable bottom-16 select and sets a ready flag (proven mechanism).
//  - Phase B: pop eighth-plane gather tickets (16 pools of 128). Blocks
//    flow from their last mean unit straight into gather work: no kernel
//    boundary, no wave ramp, early batches' units are long ready (spin only
//    in the final straggler window). Deadlock-free by work conservation.
//  - Self-reset: global exit ticket; the last block to exit resets all
//    counters (race-free: nobody can pop anymore). ONE graph node.

#define B 16
#define C 256
#define HW 16384          // 128*128
#define K 16
#define GRID 1184         // 148 * 8, one full wave
#define GU (K * 8)        // 128 gather units per batch (eighth planes)

__device__ float g_weight[B * C];
__device__ int   g_idx[B * K];
__device__ int   g_mtick[B];      // mean pool tickets      (self-reset)
__device__ int   g_mdone[B];      // mean completions       (self-reset)
__device__ int   g_ready[B];      // select published       (self-reset)
__device__ int   g_gtick[B];      // gather pool tickets    (self-reset)
__device__ int   g_exit;          // exit ticket            (self-reset)

__global__ __launch_bounds__(256, 8) void fused_kernel(const float* __restrict__ x,
                                                       float* __restrict__ out) {
    const int bid = blockIdx.x;
    const int t   = threadIdx.x;

    __shared__ int   s_unit;
    __shared__ float sred[8];
    __shared__ int   s_last;
    __shared__ float sw[C];

    // ===================== Phase A: means (ticket pools) =====================
    for (int pi = 0; pi < B; ++pi) {
        const int b = (bid + pi) & (B - 1);            // spread pool contention
        for (;;) {
            if (t == 0) s_unit = atomicAdd(&g_mtick[b], 1);
            __syncthreads();
            const int u = s_unit;
            __syncthreads();                           // protect s_unit reuse
            if (u >= C) break;

            const int plane = b * C + u;
            const float4* __restrict__ p =
                reinterpret_cast<const float4*>(x + (size_t)plane * HW);
            float s0 = 0.f, s1 = 0.f, s2 = 0.f, s3 = 0.f;
#pragma unroll
            for (int i = 0; i < 16; i += 4) {
                float4 v0 = __ldg(&p[t + (i + 0) * 256]);
                float4 v1 = __ldg(&p[t + (i + 1) * 256]);
                float4 v2 = __ldg(&p[t + (i + 2) * 256]);
                float4 v3 = __ldg(&p[t + (i + 3) * 256]);
                s0 += (v0.x + v0.y) + (v0.z + v0.w);
                s1 += (v1.x + v1.y) + (v1.z + v1.w);
                s2 += (v2.x + v2.y) + (v2.z + v2.w);
                s3 += (v3.x + v3.y) + (v3.z + v3.w);
            }
            float s = (s0 + s1) + (s2 + s3);
#pragma unroll
            for (int off = 16; off > 0; off >>= 1)
                s += __shfl_down_sync(0xFFFFFFFFu, s, off);

            if ((t & 31) == 0) sred[t >> 5] = s;
            __syncthreads();
            if (t < 8) {
                float v = sred[t];
#pragma unroll
                for (int off = 4; off > 0; off >>= 1)
                    v += __shfl_down_sync(0xFFu, v, off);
                if (t == 0) {
                    g_weight[plane] = v * (1.0f / (float)HW);
                    __threadfence();                   // publish mean
                    const int old = atomicAdd(&g_mdone[b], 1);
                    s_last = (old == C - 1);           // last finisher
                }
            }
            __syncthreads();

            if (s_last) {
                // ---- stable bottom-16 select for batch b ----
                __threadfence();
                sw[t] = __ldcg(&g_weight[b * C + t]);
                __syncthreads();
                const float v = sw[t];
                int rank = 0;
#pragma unroll 8
                for (int j = 0; j < C; ++j) {
                    const float u2 = sw[j];
                    rank += (u2 < v) || (u2 == v && j < t);
                }
                if (rank < K) g_idx[b * K + rank] = t;
                __syncthreads();
                if (t == 0) {
                    __threadfence();                   // publish g_idx
                    atomicExch(&g_ready[b], 1);
                }
                __syncthreads();
            }
        }
    }

    // ===================== Phase B: gather (ticket pools) ====================
    for (int pi = 0; pi < B; ++pi) {
        const int b = (bid + pi) & (B - 1);
        for (;;) {
            if (t == 0) s_unit = atomicAdd(&g_gtick[b], 1);
            __syncthreads();
            const int u = s_unit;
            __syncthreads();
            if (u >= GU) break;

            if (t == 0) {
                while (atomicAdd(&g_ready[b], 0) == 0) __nanosleep(64);
            }
            __syncthreads();                           // acquire for block

            const int k     = u >> 3;
            const int q     = u & 7;
            const int plane = b * K + k;
            const int c     = __ldcg(&g_idx[plane]);

            const float4* __restrict__ src = reinterpret_cast<const float4*>(
                x + ((size_t)b * C + c) * HW) + q * 512;
            float4* __restrict__ dst = reinterpret_cast<float4*>(
                out + (size_t)plane * HW) + q * 512;

            float4 w0 = __ldg(&src[t]);
            float4 w1 = __ldg(&src[t + 256]);
            __stcs(&dst[t],       w0);
            __stcs(&dst[t + 256], w1);
        }
    }

    // ===================== Exit ticket + race-free reset =====================
    __syncthreads();
    if (t == 0) {
        const int old = atomicAdd(&g_exit, 1);
        if (old == GRID - 1) {                         // absolute last block
#pragma unroll
            for (int b = 0; b < B; ++b) {
                g_mtick[b] = 0;
                g_mdone[b] = 0;
                g_ready[b] = 0;
                g_gtick[b] = 0;
            }
            __threadfence();
            atomicExch(&g_exit, 0);                    // replay-safe
        }
    }
}

// ---------------------------------------------------------------------------
extern "C" void kernel_launch(void* const* d_in, const int* in_sizes, int n_in,
                              void* d_out, int out_size) {
    const float* x = (const float*)d_in[0];
    float* out = (float*)d_out;

    fused_kernel<<<GRID, 256>>>(x, out);
}

// round 13
// speedup vs baseline: 1.1331x; 1.1331x over previous
#include <cuda_runtime.h>
#include <cuda_bf16.h>
#include <cstdint>

// Problem: x [16, 256, 128, 128] f32.
//  1) weight[b,c] = mean over H,W
//  2) idx[b,:] = argsort(weight[b]) ascending, take first 16 (stable)
//  3) out[b,k,:,:] = x[b, idx[b,k], :, :]
//
// R13 (= R12 resubmit after infra failure, minor cleanup):
//  - 4096 mean blocks: untouched 80%-of-peak mean loop; last finisher per
//    batch does the stable bottom-16 select and atomicOr's a READY BITMASK.
//  - OPPORTUNISTIC GATHER: after its mean, each block reads the ready mask
//    once (non-blocking) and, if a ready batch has gather tickets left,
//    copies ONE 16KB quarter-plane unit. Volunteers never spin and are
//    already resident => gather absorbed into the mean phase at zero slot
//    cost (fixes R4/R8/R9 spin-theft and R11 barrier-drain).
//  - 256 tail blocks sweep all pools to exhaustion (bounded spin only for
//    the last batches; 928+ slots keep serving mean blocks => deadlock-free).
//  - Exit-ticket self-reset (race-free: last exiting block resets) =>
//    ONE graph node, no memset.

#define B 16
#define C 256
#define HW 16384          // 128*128
#define K 16
#define MEAN_BLOCKS 4096
#define TAIL_BLOCKS 256
#define UPB 64            // gather units per batch (16 planes x 4 quarters)

__device__ float    g_weight[B * C];
__device__ int      g_idx[B * K];
__device__ int      g_mdone[B];       // mean completions per batch (self-reset)
__device__ unsigned g_ready_mask;     // bit b = batch b select published
__device__ int      g_gtick[B];       // gather ticket pools (self-reset)
__device__ int      g_exit;           // exit ticket (self-reset)

// Copy one quarter-plane (16KB) of the rank-k selected channel of batch b.
__device__ __forceinline__ void gather_unit(const float* __restrict__ x,
                                            float* __restrict__ out,
                                            int b, int u, int t) {
    const int k     = u >> 2;
    const int q     = u & 3;
    const int plane = b * K + k;
    const int c     = __ldcg(&g_idx[plane]);

    const float4* __restrict__ src = reinterpret_cast<const float4*>(
        x + ((size_t)b * C + c) * HW) + q * 1024;
    float4* __restrict__ dst = reinterpret_cast<float4*>(
        out + (size_t)plane * HW) + q * 1024;

    float4 w0 = __ldg(&src[t]);
    float4 w1 = __ldg(&src[t + 256]);
    float4 w2 = __ldg(&src[t + 512]);
    float4 w3 = __ldg(&src[t + 768]);
    __stcs(&dst[t],       w0);
    __stcs(&dst[t + 256], w1);
    __stcs(&dst[t + 512], w2);
    __stcs(&dst[t + 768], w3);
}

__global__ __launch_bounds__(256, 8) void fused_kernel(const float* __restrict__ x,
                                                       float* __restrict__ out) {
    const int bid = blockIdx.x;
    const int t   = threadIdx.x;

    __shared__ int      s_u;
    __shared__ unsigned s_mask;

    if (bid < MEAN_BLOCKS) {
        // ================= Phase A: mean of plane bid =================
        const int b = bid >> 8;
        {
            const float4* __restrict__ p =
                reinterpret_cast<const float4*>(x + (size_t)bid * HW);
            float s0 = 0.f, s1 = 0.f, s2 = 0.f, s3 = 0.f;
#pragma unroll
            for (int i = 0; i < 16; i += 4) {
                float4 v0 = __ldg(&p[t + (i + 0) * 256]);
                float4 v1 = __ldg(&p[t + (i + 1) * 256]);
                float4 v2 = __ldg(&p[t + (i + 2) * 256]);
                float4 v3 = __ldg(&p[t + (i + 3) * 256]);
                s0 += (v0.x + v0.y) + (v0.z + v0.w);
                s1 += (v1.x + v1.y) + (v1.z + v1.w);
                s2 += (v2.x + v2.y) + (v2.z + v2.w);
                s3 += (v3.x + v3.y) + (v3.z + v3.w);
            }
            float s = (s0 + s1) + (s2 + s3);
#pragma unroll
            for (int off = 16; off > 0; off >>= 1)
                s += __shfl_down_sync(0xFFFFFFFFu, s, off);

            __shared__ float sred[8];
            __shared__ int   s_last;
            if ((t & 31) == 0) sred[t >> 5] = s;
            __syncthreads();
            if (t < 8) {
                float v = sred[t];
#pragma unroll
                for (int off = 4; off > 0; off >>= 1)
                    v += __shfl_down_sync(0xFFu, v, off);
                if (t == 0) {
                    g_weight[bid] = v * (1.0f / (float)HW);
                    __threadfence();                   // publish mean
                    const int old = atomicAdd(&g_mdone[b], 1);
                    s_last = (old == C - 1);           // last finisher
                }
            }
            __syncthreads();

            if (s_last) {
                // ---- stable bottom-16 select for batch b ----
                __threadfence();
                __shared__ float sw[C];
                sw[t] = __ldcg(&g_weight[b * C + t]);
                __syncthreads();
                const float v = sw[t];
                int rank = 0;
#pragma unroll 8
                for (int j = 0; j < C; ++j) {
                    const float u2 = sw[j];
                    rank += (u2 < v) || (u2 == v && j < t);
                }
                if (rank < K) g_idx[b * K + rank] = t;
                __syncthreads();
                if (t == 0) {
                    __threadfence();                   // publish g_idx
                    atomicOr(&g_ready_mask, 1u << b);  // announce ready
                }
            }
        }

        // ======= opportunistic gather: ONE unit from a ready batch =======
        if (t == 0) s_mask = atomicAdd(&g_ready_mask, 0u);  // non-blocking read
        __syncthreads();
        const unsigned mask = s_mask;
        if (mask) {
            // try up to 2 ready pools (first may be drained)
            int tried = 0;
            for (int pi = 0; pi < B && tried < 2; ++pi) {
                const int gb = (bid + pi) & (B - 1);
                if (!((mask >> gb) & 1u)) continue;
                if (t == 0) s_u = atomicAdd(&g_gtick[gb], 1);
                __syncthreads();
                const int u = s_u;
                __syncthreads();
                ++tried;
                if (u < UPB) { gather_unit(x, out, gb, u, t); break; }
            }
        }
    } else {
        // ================= Phase B: tail sweep (256 blocks) =================
        const int r = bid - MEAN_BLOCKS;
        for (int pi = 0; pi < B; ++pi) {
            const int gb = (r + pi) & (B - 1);
            for (;;) {
                if (t == 0) s_u = atomicAdd(&g_gtick[gb], 1);
                __syncthreads();
                const int u = s_u;
                __syncthreads();
                if (u >= UPB) break;
                if (t == 0) {
                    while (((atomicAdd(&g_ready_mask, 0u) >> gb) & 1u) == 0)
                        __nanosleep(128);
                }
                __syncthreads();                       // acquire for block
                gather_unit(x, out, gb, u, t);
            }
        }
    }

    // ================= exit ticket + race-free reset =================
    __syncthreads();
    if (t == 0) {
        const int old = atomicAdd(&g_exit, 1);
        if (old == MEAN_BLOCKS + TAIL_BLOCKS - 1) {    // absolute last block
#pragma unroll
            for (int b2 = 0; b2 < B; ++b2) {
                g_mdone[b2] = 0;
                g_gtick[b2] = 0;
            }
            g_ready_mask = 0u;
            __threadfence();
            atomicExch(&g_exit, 0);                    // replay-safe
        }
    }
}

// ---------------------------------------------------------------------------
extern "C" void kernel_launch(void* const* d_in, const int* in_sizes, int n_in,
                              void* d_out, int out_size) {
    const float* x = (const float*)d_in[0];
    float* out = (float*)d_out;

    fused_kernel<<<MEAN_BLOCKS + TAIL_BLOCKS, 256>>>(x, out);
}

// round 14
// speedup vs baseline: 1.3418x; 1.1842x over previous
#include <cuda_runtime.h>
#include <cuda_bf16.h>
#include <cstdint>

// Problem: x [16, 256, 128, 128] f32.
//  1) weight[b,c] = mean over H,W
//  2) idx[b,:] = argsort(weight[b]) ascending, take first 16 (stable)
//  3) out[b,k,:,:] = x[b, idx[b,k], :, :]
//
// R14 = R10 (best measured: pristine mean pass, gathers strictly after,
// self-resetting sync, ONE graph node) with the gather rewritten as
// hardware-pipelined bulk-async copies:
//   each gather block: cp.async.bulk GMEM->SMEM (16KB, mbarrier) ->
//                      cp.async.bulk SMEM->GMEM (bulk_group).
// One thread per block issues everything; 16KB in flight per block fixes
// the latency-bound drain tail (R10: 8.6us @ 3.7TB/s for 32MiB).
// Static SMEM 16.5KB x 8 blocks = 132KB < 228KB: mean occupancy untouched.

#define B 16
#define C 256
#define HW 16384          // 128*128
#define K 16
#define MEAN_BLOCKS 4096
#define GATHER_BLOCKS 1024   // 4 per output plane (16KB quarter planes)
#define QBYTES 16384         // bytes per gather unit

__device__ float    g_weight[B * C];
__device__ int      g_idx[B * K];
__device__ int      g_mdone[B];       // mean completions (self-reset)
__device__ unsigned g_ready_mask;     // bit b = select published (self-reset)
__device__ int      g_exit;           // exit ticket (self-reset)

// ---- bulk-async helpers ----------------------------------------------------
__device__ __forceinline__ uint32_t smem_u32(const void* p) {
    uint32_t a;
    asm("{ .reg .u64 t; cvta.to.shared.u64 t, %1; cvt.u32.u64 %0, t; }"
        : "=r"(a) : "l"(p));
    return a;
}
__device__ __forceinline__ void mbar_init(uint32_t a) {
    asm volatile("mbarrier.init.shared.b64 [%0], 1;" :: "r"(a) : "memory");
}
__device__ __forceinline__ void mbar_expect(uint32_t a, uint32_t bytes) {
    asm volatile("mbarrier.arrive.expect_tx.shared.b64 _, [%0], %1;"
                 :: "r"(a), "r"(bytes) : "memory");
}
__device__ __forceinline__ void mbar_wait(uint32_t a) {    // phase parity 0
    uint32_t done = 0;
    while (!done) {
        asm volatile(
            "{ .reg .pred p;\n\t"
            "mbarrier.try_wait.parity.shared.b64 p, [%1], 0;\n\t"
            "selp.b32 %0, 1, 0, p; }"
            : "=r"(done) : "r"(a) : "memory");
    }
}
__device__ __forceinline__ void bulk_g2s(uint32_t smem, const void* gsrc,
                                         uint32_t bytes, uint32_t mbar) {
    asm volatile(
        "cp.async.bulk.shared::cluster.global.mbarrier::complete_tx::bytes "
        "[%0], [%1], %2, [%3];"
        :: "r"(smem), "l"(gsrc), "r"(bytes), "r"(mbar) : "memory");
}
__device__ __forceinline__ void bulk_s2g(void* gdst, uint32_t smem,
                                         uint32_t bytes) {
    asm volatile("cp.async.bulk.global.shared::cta.bulk_group [%0], [%1], %2;"
                 :: "l"(gdst), "r"(smem), "r"(bytes) : "memory");
    asm volatile("cp.async.bulk.commit_group;" ::: "memory");
    asm volatile("cp.async.bulk.wait_group.read 0;" ::: "memory");
}

__global__ __launch_bounds__(256, 8) void fused_kernel(const float* __restrict__ x,
                                                       float* __restrict__ out) {
    const int bid = blockIdx.x;
    const int t   = threadIdx.x;

    __shared__ alignas(128) char s_buf[QBYTES];       // 16KB bounce buffer
    __shared__ alignas(8)  uint64_t s_mbar;

    if (bid < MEAN_BLOCKS) {
        // ================= Phase A: mean of plane bid (pristine) =============
        const int b = bid >> 8;
        const float4* __restrict__ p =
            reinterpret_cast<const float4*>(x + (size_t)bid * HW);
        float s0 = 0.f, s1 = 0.f, s2 = 0.f, s3 = 0.f;
#pragma unroll
        for (int i = 0; i < 16; i += 4) {
            float4 v0 = __ldg(&p[t + (i + 0) * 256]);
            float4 v1 = __ldg(&p[t + (i + 1) * 256]);
            float4 v2 = __ldg(&p[t + (i + 2) * 256]);
            float4 v3 = __ldg(&p[t + (i + 3) * 256]);
            s0 += (v0.x + v0.y) + (v0.z + v0.w);
            s1 += (v1.x + v1.y) + (v1.z + v1.w);
            s2 += (v2.x + v2.y) + (v2.z + v2.w);
            s3 += (v3.x + v3.y) + (v3.z + v3.w);
        }
        float s = (s0 + s1) + (s2 + s3);
#pragma unroll
        for (int off = 16; off > 0; off >>= 1)
            s += __shfl_down_sync(0xFFFFFFFFu, s, off);

        __shared__ float sred[8];
        __shared__ int   s_last;
        if ((t & 31) == 0) sred[t >> 5] = s;
        __syncthreads();
        if (t < 8) {
            float v = sred[t];
#pragma unroll
            for (int off = 4; off > 0; off >>= 1)
                v += __shfl_down_sync(0xFFu, v, off);
            if (t == 0) {
                g_weight[bid] = v * (1.0f / (float)HW);
                __threadfence();                       // publish mean
                const int old = atomicAdd(&g_mdone[b], 1);
                s_last = (old == C - 1);               // last finisher
            }
        }
        __syncthreads();

        if (s_last) {
            // ---- stable bottom-16 select for batch b ----
            __threadfence();
            __shared__ float sw[C];
            sw[t] = __ldcg(&g_weight[b * C + t]);
            __syncthreads();
            const float v = sw[t];
            int rank = 0;
#pragma unroll 8
            for (int j = 0; j < C; ++j) {
                const float u2 = sw[j];
                rank += (u2 < v) || (u2 == v && j < t);
            }
            if (rank < K) g_idx[b * K + rank] = t;
            __syncthreads();
            if (t == 0) {
                __threadfence();                       // publish g_idx
                atomicOr(&g_ready_mask, 1u << b);      // announce ready
            }
        }
        __syncthreads();
        if (t == 0) {
            const int old = atomicAdd(&g_exit, 1);
            if (old == MEAN_BLOCKS + GATHER_BLOCKS - 1) {
#pragma unroll
                for (int b2 = 0; b2 < B; ++b2) g_mdone[b2] = 0;
                g_ready_mask = 0u;
                __threadfence();
                atomicExch(&g_exit, 0);                // replay-safe
            }
        }
        return;
    }

    // ============ Phase B: gather via bulk-async (thread 0 only) ============
    // No __syncthreads in this path: threads 1..255 exit immediately.
    if (t != 0) return;

    const int g     = bid - MEAN_BLOCKS;               // 0..1023
    const int plane = g >> 2;                          // 0..255
    const int q     = g & 3;                           // quarter of plane
    const int b     = plane >> 4;

    // bounded wait: only the last batches' gathers can arrive early
    while (((atomicAdd(&g_ready_mask, 0u) >> b) & 1u) == 0) __nanosleep(128);

    const int c = __ldcg(&g_idx[plane]);

    const char* gsrc = reinterpret_cast<const char*>(
        x + ((size_t)b * C + c) * HW) + (size_t)q * QBYTES;
    char* gdst = reinterpret_cast<char*>(
        out + (size_t)plane * HW) + (size_t)q * QBYTES;

    const uint32_t smem = smem_u32(s_buf);
    const uint32_t mbar = smem_u32(&s_mbar);

    mbar_init(mbar);
    asm volatile("fence.proxy.async.shared::cta;" ::: "memory");
    mbar_expect(mbar, QBYTES);
    bulk_g2s(smem, gsrc, QBYTES, mbar);                // 16KB in flight
    mbar_wait(mbar);
    asm volatile("fence.proxy.async.shared::cta;" ::: "memory");
    bulk_s2g(gdst, smem, QBYTES);                      // pipelined store

    // exit ticket + race-free reset
    const int old = atomicAdd(&g_exit, 1);
    if (old == MEAN_BLOCKS + GATHER_BLOCKS - 1) {
#pragma unroll
        for (int b2 = 0; b2 < B; ++b2) g_mdone[b2] = 0;
        g_ready_mask = 0u;
        __threadfence();
        atomicExch(&g_exit, 0);                        // replay-safe
    }
}

// ---------------------------------------------------------------------------
extern "C" void kernel_launch(void* const* d_in, const int* in_sizes, int n_in,
                              void* d_out, int out_size) {
    const float* x = (const float*)d_in[0];
    float* out = (float*)d_out;

    fused_kernel<<<MEAN_BLOCKS + GATHER_BLOCKS, 256>>>(x, out);
}

// round 15
// speedup vs baseline: 1.3441x; 1.0017x over previous
#include <cuda_runtime.h>
#include <cuda_bf16.h>
#include <cstdint>

// Problem: x [16, 256, 128, 128] f32.
//  1) weight[b,c] = mean over H,W
//  2) idx[b,:] = argsort(weight[b]) ascending, take first 16 (stable)
//  3) out[b,k,:,:] = x[b, idx[b,k], :, :]
//
// R15 = R10 structure (pristine means first, gathers strictly after,
// self-reset sync, ONE graph node) with HALF-PLANE mean blocks:
//  - 8192 mean blocks of 32KB each (lifetime ~6us vs 12us) halve the
//    end-of-stream drain ramp where DRAM desaturates — the measured 4us
//    gap between R10's 51.1us kernel and the 47.1us traffic floor.
//  - Per-plane sum = atomicAdd of exactly TWO partials (commutative =>
//    deterministic). Ranking uses raw sums (== ranking means).
//  - Select by last finisher (ticket==511); it resets its batch's weights
//    and ticket => replay-safe without a memset node.
//  - Gather unchanged from R10 (2048 x 8KB units, 2 float4/thread, __stcs).

#define B 16
#define C 256
#define HW 16384          // 128*128
#define K 16
#define MEAN_BLOCKS 8192     // 2 per plane (32KB halves)
#define GATHER_BLOCKS 2048   // 8 per output plane (8KB eighths)

__device__ float    g_weight[B * C];   // plane SUMS (zeroed by select block)
__device__ int      g_idx[B * K];
__device__ int      g_mdone[B];        // half-plane tickets (reset by select)
__device__ unsigned g_ready_mask;      // bit b = select published
__device__ int      g_exit;            // exit ticket (self-reset)

__global__ __launch_bounds__(256, 8) void fused_kernel(const float* __restrict__ x,
                                                       float* __restrict__ out) {
    const int bid = blockIdx.x;
    const int t   = threadIdx.x;

    if (bid < MEAN_BLOCKS) {
        // ============ Phase A: half-plane partial sum (32KB/block) ============
        const int plane = bid >> 1;                    // 0..4095
        const int half  = bid & 1;
        const int b     = plane >> 8;

        const float4* __restrict__ p = reinterpret_cast<const float4*>(
            x + (size_t)plane * HW) + half * 2048;
        float s0 = 0.f, s1 = 0.f, s2 = 0.f, s3 = 0.f;
#pragma unroll
        for (int i = 0; i < 8; i += 4) {
            float4 v0 = __ldg(&p[t + (i + 0) * 256]);
            float4 v1 = __ldg(&p[t + (i + 1) * 256]);
            float4 v2 = __ldg(&p[t + (i + 2) * 256]);
            float4 v3 = __ldg(&p[t + (i + 3) * 256]);
            s0 += (v0.x + v0.y) + (v0.z + v0.w);
            s1 += (v1.x + v1.y) + (v1.z + v1.w);
            s2 += (v2.x + v2.y) + (v2.z + v2.w);
            s3 += (v3.x + v3.y) + (v3.z + v3.w);
        }
        float s = (s0 + s1) + (s2 + s3);
#pragma unroll
        for (int off = 16; off > 0; off >>= 1)
            s += __shfl_down_sync(0xFFFFFFFFu, s, off);

        __shared__ float sred[8];
        __shared__ int   s_last;
        if ((t & 31) == 0) sred[t >> 5] = s;
        __syncthreads();
        if (t < 8) {
            float v = sred[t];
#pragma unroll
            for (int off = 4; off > 0; off >>= 1)
                v += __shfl_down_sync(0xFFu, v, off);
            if (t == 0) {
                atomicAdd(&g_weight[plane], v);        // 2 partials: deterministic
                __threadfence();                       // publish partial
                const int old = atomicAdd(&g_mdone[b], 1);
                s_last = (old == 2 * C - 1);           // last of 512 halves
            }
        }
        __syncthreads();
        if (!s_last) return;

        // ---- last half-block of batch b: stable bottom-16 on sums ----
        __threadfence();                               // acquire all partials
        __shared__ float sw[C];
        sw[t] = __ldcg(&g_weight[b * C + t]);
        __syncthreads();

        const float v = sw[t];
        int rank = 0;
#pragma unroll 8
        for (int j = 0; j < C; ++j) {
            const float u = sw[j];
            rank += (u < v) || (u == v && j < t);
        }
        if (rank < K) g_idx[b * K + rank] = t;

        g_weight[b * C + t] = 0.0f;                    // reset sums for replay
        __syncthreads();
        if (t == 0) {
            atomicExch(&g_mdone[b], 0);                // reset ticket for replay
            __threadfence();                           // publish g_idx
            atomicOr(&g_ready_mask, 1u << b);          // announce ready
        }
        return;
    }

    // ============ Phase B: gather, 2048 eighth-plane blocks (R10) ============
    const int g     = bid - MEAN_BLOCKS;               // 0..2047
    const int plane = g >> 3;                          // 0..255
    const int q     = g & 7;                           // eighth of plane
    const int b     = plane >> 4;

    if (t == 0) {
        while (((atomicAdd(&g_ready_mask, 0u) >> b) & 1u) == 0) __nanosleep(64);
    }
    __syncthreads();                                   // acquire for block

    const int c = __ldcg(&g_idx[plane]);

    const float4* __restrict__ src = reinterpret_cast<const float4*>(
        x + ((size_t)b * C + c) * HW) + q * 512;
    float4* __restrict__ dst = reinterpret_cast<float4*>(
        out + (size_t)plane * HW) + q * 512;

    float4 w0 = __ldg(&src[t]);
    float4 w1 = __ldg(&src[t + 256]);
    __stcs(&dst[t],       w0);
    __stcs(&dst[t + 256], w1);

    // exit ticket: last GATHER block resets the ready mask (all gathers done
    // => mask no longer needed this launch)
    __syncthreads();
    if (t == 0) {
        const int old = atomicAdd(&g_exit, 1);
        if (old == GATHER_BLOCKS - 1) {
            g_ready_mask = 0u;
            __threadfence();
            atomicExch(&g_exit, 0);                    // replay-safe
        }
    }
}

// ---------------------------------------------------------------------------
extern "C" void kernel_launch(void* const* d_in, const int* in_sizes, int n_in,
                              void* d_out, int out_size) {
    const float* x = (const float*)d_in[0];
    float* out = (float*)d_out;

    fused_kernel<<<MEAN_BLOCKS + GATHER_BLOCKS, 256>>>(x, out);
}